// round 6
// baseline (speedup 1.0000x reference)
#include <cuda_runtime.h>
#include <cuda_fp16.h>
#include <cstdint>

#define N_IN     256
#define DDEG     8
#define N_OUT    64
#define M_TILE   128
#define N_CHUNKS 32

// smem byte offsets: A double-buffered 16KB each, B 8KB each
#define SMA(p)   ((p) * 16384)
#define SMB(p)   (32768 + (p) * 8192)
#define SM_TOTAL 49152

// A-tile in-block swizzle: slot for (fr, c) within a (ks, mtile) 512B block.
// Conflict-free for generator STS.128 (8-lane phase spans fr) and consumer
// LDS.128 (8-lane phase spans c and fr-pairs).
#define ASWZ(fr, c) ((((fr) + 2 * (c)) & 7) + 8 * (c))

// B prepacked as exact per-chunk smem fragment images: 32 chunks x 4096 halves
__device__ __half g_Bpack[N_CHUNKS * 4096];

// Layout: [ch][ks(4)][ng(4)][lane(32)][e(8 halves)]; uint4 slot = frags of
// n-tiles {2ng, 2ng+1}: {nt0.b01, nt0.b23, nt1.b01, nt1.b23}
__global__ void repack_kernel(const float* __restrict__ c_basis) {
    int idx = blockIdx.x * 256 + threadIdx.x;          // 131072 total
    int e    = idx & 7;
    int lane = (idx >> 3) & 31;
    int ng   = (idx >> 8) & 3;
    int ks   = (idx >> 10) & 3;
    int ch   = idx >> 12;
    int nt = ng * 2 + (e >> 2);
    int bp = (e >> 1) & 1;                             // b01 vs b23 (k +8)
    int h  = e & 1;
    int k  = ks * 16 + bp * 8 + (lane & 3) * 2 + h;    // k within chunk
    int n  = nt * 8 + (lane >> 2);
    int kg = ch * 64 + k;
    int i = kg >> 3, d = kg & 7;
    g_Bpack[idx] = __float2half_rn(c_basis[(n * N_IN + i) * DDEG + d]);
}

#define MMA16816(ac, A0, A1, A2, A3, B0, B1)                                  \
    asm volatile(                                                             \
        "mma.sync.aligned.m16n8k16.row.col.f32.f16.f16.f32 "                  \
        "{%0,%1,%2,%3}, {%4,%5,%6,%7}, {%8,%9}, {%0,%1,%2,%3};"               \
        : "+f"((ac)[0]), "+f"((ac)[1]), "+f"((ac)[2]), "+f"((ac)[3])          \
        : "r"(A0), "r"(A1), "r"(A2), "r"(A3), "r"(B0), "r"(B1))

__device__ __forceinline__ void cp_async16(uint32_t saddr, const void* gptr) {
    asm volatile("cp.async.ca.shared.global [%0], [%1], 16;"
                 :: "r"(saddr), "l"(gptr) : "memory");
}

// P1..P8 of tanh(xval), packed as 4 half2 regs: hp[c] = (P_{2c+1}, P_{2c+2})
__device__ __forceinline__ void leg8(float xval, uint32_t hp[4]) {
    float e2 = __expf(2.0f * xval);
    float t  = 1.0f - 2.0f / (e2 + 1.0f);
    float pv[8];
    pv[0] = t;
    float pp = 1.0f, pc = t;
    #pragma unroll
    for (int d = 1; d < 8; d++) {
        float kk = (float)(d + 1);
        float a_ = (2.0f * kk - 1.0f) / kk;
        float b_ = (kk - 1.0f) / kk;
        float pn = a_ * t * pc - b_ * pp;
        pv[d] = pn; pp = pc; pc = pn;
    }
    #pragma unroll
    for (int cc = 0; cc < 4; cc++) {
        __half2 h2 = __floats2half2_rn(pv[2 * cc], pv[2 * cc + 1]);
        hp[cc] = *(uint32_t*)&h2;
    }
}

extern __shared__ __align__(128) char sm[];

__global__ __launch_bounds__(256, 3)
void kan_fp16_kernel(const float* __restrict__ x, const float* __restrict__ bias,
                     float* __restrict__ y, int batch) {
    const int tid  = threadIdx.x;
    const int lane = tid & 31;
    const int wid  = tid >> 5;
    const int wm   = wid & 3;          // m32 group (rows wm*32..+31)
    const int wn   = wid >> 2;         // n32 group (cols wn*32..+31)
    const int rowBase = blockIdx.x * M_TILE;
    const uint32_t sbase = (uint32_t)__cvta_generic_to_shared(sm);

    // ---- gen mapping: thread -> (fr, mtile, ks) = one full uint4 A-slot ----
    // covers rows {mt*16+fr, +8} x feats {2ks, 2ks+1} of the chunk
    const int fr_g = tid & 7;
    const int mt_g = (tid >> 3) & 7;
    const int ks_g = tid >> 6;                          // 0..3
    int rl = mt_g * 16 + fr_g;
    int rg0 = rowBase + rl;      if (rg0 > batch - 1) rg0 = batch - 1;
    int rg1 = rowBase + rl + 8;  if (rg1 > batch - 1) rg1 = batch - 1;
    const float* xp0 = x + (size_t)rg0 * N_IN + 2 * ks_g;
    const float* xp1 = x + (size_t)rg1 * N_IN + 2 * ks_g;
    const uint32_t ablk = (uint32_t)((ks_g * 8 + mt_g) * 512);
    uint32_t aslot[4];
    #pragma unroll
    for (int cc = 0; cc < 4; cc++) aslot[cc] = ablk + ASWZ(fr_g, cc) * 16;

    // ---- consumer fragment indices ----
    const int c  = lane & 3;
    const int fr = lane >> 2;

    float acc[2][4][4] = {};

    // ---- prolog: cp.async stage B(0), prefetch x(0) ----
    {
        const char* src = (const char*)g_Bpack;
        cp_async16(sbase + SMB(0) + tid * 16,         src + tid * 16);
        cp_async16(sbase + SMB(0) + (tid + 256) * 16, src + (tid + 256) * 16);
        asm volatile("cp.async.commit_group;" ::: "memory");
    }
    float2 xv0 = *(const float2*)xp0;     // row rl,   feats (2ks, 2ks+1)
    float2 xv1 = *(const float2*)xp1;     // row rl+8, feats (2ks, 2ks+1)

    for (int ch = 0; ch < N_CHUNKS; ch++) {
        const int p = ch & 1;

        // ---- generate A(ch): 4 (row,feat) recurrences -> 4x STS.128 ----
        {
            char* Ab = sm + SMA(p);
            float xf00 = xv0.x, xf01 = xv0.y, xf10 = xv1.x, xf11 = xv1.y;
            if (ch + 1 < N_CHUNKS) {
                xv0 = *(const float2*)(xp0 + (ch + 1) * 8);
                xv1 = *(const float2*)(xp1 + (ch + 1) * 8);
            }
            uint32_t h00[4], h01[4], h10[4], h11[4];
            leg8(xf00, h00);   // (rlow,  i0)
            leg8(xf01, h01);   // (rlow,  i1)
            leg8(xf10, h10);   // (rhigh, i0)
            leg8(xf11, h11);   // (rhigh, i1)
            #pragma unroll
            for (int cc = 0; cc < 4; cc++) {
                uint4 v = make_uint4(h00[cc], h01[cc], h10[cc], h11[cc]);
                *(uint4*)(Ab + aslot[cc]) = v;
            }
        }

        // ---- B(ch) arrived + A(ch) visible ----
        asm volatile("cp.async.wait_group 0;" ::: "memory");
        __syncthreads();

        // ---- prefetch B(ch+1) (safe: all warps finished MMA(ch-1)) ----
        if (ch + 1 < N_CHUNKS) {
            const char* src = (const char*)g_Bpack + (size_t)(ch + 1) * 8192;
            cp_async16(sbase + SMB(p ^ 1) + tid * 16,         src + tid * 16);
            cp_async16(sbase + SMB(p ^ 1) + (tid + 256) * 16, src + (tid + 256) * 16);
            asm volatile("cp.async.commit_group;" ::: "memory");
        }

        // ---- MMA: 4 k-steps x (2 m-tiles x 4 n-tiles) m16n8k16 ----
        {
            const char* Ar = sm + SMA(p);
            const char* Br = sm + SMB(p);
            #pragma unroll
            for (int ks = 0; ks < 4; ks++) {
                uint4 a0 = *(const uint4*)(Ar + (ks * 8 + wm * 2 + 0) * 512 + ASWZ(fr, c) * 16);
                uint4 a1 = *(const uint4*)(Ar + (ks * 8 + wm * 2 + 1) * 512 + ASWZ(fr, c) * 16);
                uint4 b0 = *(const uint4*)(Br + ((ks * 4 + wn * 2 + 0) * 32 + lane) * 16);
                uint4 b1 = *(const uint4*)(Br + ((ks * 4 + wn * 2 + 1) * 32 + lane) * 16);
                // A operand order: (rl-klo, rh-klo, rl-khi, rh-khi) = (x, z, y, w)
                MMA16816(acc[0][0], a0.x, a0.z, a0.y, a0.w, b0.x, b0.y);
                MMA16816(acc[0][1], a0.x, a0.z, a0.y, a0.w, b0.z, b0.w);
                MMA16816(acc[0][2], a0.x, a0.z, a0.y, a0.w, b1.x, b1.y);
                MMA16816(acc[0][3], a0.x, a0.z, a0.y, a0.w, b1.z, b1.w);
                MMA16816(acc[1][0], a1.x, a1.z, a1.y, a1.w, b0.x, b0.y);
                MMA16816(acc[1][1], a1.x, a1.z, a1.y, a1.w, b0.z, b0.w);
                MMA16816(acc[1][2], a1.x, a1.z, a1.y, a1.w, b1.x, b1.y);
                MMA16816(acc[1][3], a1.x, a1.z, a1.y, a1.w, b1.z, b1.w);
            }
        }
    }

    // ---- epilogue: bias + store ----
    #pragma unroll
    for (int t = 0; t < 2; t++) {
        int r0 = rowBase + wm * 32 + t * 16 + fr;
        #pragma unroll
        for (int nt = 0; nt < 4; nt++) {
            int col = wn * 32 + nt * 8 + c * 2;
            float2 bb = *(const float2*)(bias + col);
            if (r0 < batch)
                *(float2*)(y + (size_t)r0 * N_OUT + col) =
                    make_float2(acc[t][nt][0] + bb.x, acc[t][nt][1] + bb.y);
            if (r0 + 8 < batch)
                *(float2*)(y + (size_t)(r0 + 8) * N_OUT + col) =
                    make_float2(acc[t][nt][2] + bb.x, acc[t][nt][3] + bb.y);
        }
    }
}

extern "C" void kernel_launch(void* const* d_in, const int* in_sizes, int n_in,
                              void* d_out, int out_size) {
    const float* x       = (const float*)d_in[0];
    const float* c_basis = (const float*)d_in[1];
    const float* bias    = (const float*)d_in[2];
    float* y = (float*)d_out;
    int batch = in_sizes[0] / N_IN;

    cudaFuncSetAttribute(kan_fp16_kernel,
                         cudaFuncAttributeMaxDynamicSharedMemorySize, SM_TOTAL);

    repack_kernel<<<(N_CHUNKS * 4096) / 256, 256>>>(c_basis);
    int grid = (batch + M_TILE - 1) / M_TILE;
    kan_fp16_kernel<<<grid, 256, SM_TOTAL>>>(x, bias, y, batch);
}

// round 7
// speedup vs baseline: 1.1409x; 1.1409x over previous
#include <cuda_runtime.h>
#include <cuda_fp16.h>
#include <cstdint>

#define N_IN     256
#define DDEG     8
#define N_OUT    64
#define M_TILE   128
#define N_CHUNKS 32

// smem byte offsets: A double-buffered 16KB each, B 8KB each
#define SMA(p)   ((p) * 16384)
#define SMB(p)   (32768 + (p) * 8192)
#define SM_TOTAL 49152

// A-tile in-block swizzle: slot for (fr, c) within a (ks, mtile) 512B block.
// ks-bit1 term keeps BOTH the generator's 4rowx2half STS.64 phase and the
// consumer's LDS.128 phase conflict-free.
#define ASWZ3(fr, c, ks) ((((fr) + 2 * (c) + 4 * (((ks) >> 1) & 1)) & 7) + 8 * (c))

// B prepacked as exact per-chunk smem fragment images: 32 chunks x 4096 halves
__device__ __half g_Bpack[N_CHUNKS * 4096];

// Layout: [ch][ks(4)][ng(4)][lane(32)][e(8 halves)]; uint4 slot = frags of
// n-tiles {2ng, 2ng+1}: {nt0.b01, nt0.b23, nt1.b01, nt1.b23}
__global__ void repack_kernel(const float* __restrict__ c_basis) {
    int idx = blockIdx.x * 256 + threadIdx.x;          // 131072 total
    int e    = idx & 7;
    int lane = (idx >> 3) & 31;
    int ng   = (idx >> 8) & 3;
    int ks   = (idx >> 10) & 3;
    int ch   = idx >> 12;
    int nt = ng * 2 + (e >> 2);
    int bp = (e >> 1) & 1;                             // b01 vs b23 (k +8)
    int h  = e & 1;
    int k  = ks * 16 + bp * 8 + (lane & 3) * 2 + h;    // k within chunk
    int n  = nt * 8 + (lane >> 2);
    int kg = ch * 64 + k;
    int i = kg >> 3, d = kg & 7;
    g_Bpack[idx] = __float2half_rn(c_basis[(n * N_IN + i) * DDEG + d]);
}

#define MMA16816(ac, A0, A1, A2, A3, B0, B1)                                  \
    asm volatile(                                                             \
        "mma.sync.aligned.m16n8k16.row.col.f32.f16.f16.f32 "                  \
        "{%0,%1,%2,%3}, {%4,%5,%6,%7}, {%8,%9}, {%0,%1,%2,%3};"               \
        : "+f"((ac)[0]), "+f"((ac)[1]), "+f"((ac)[2]), "+f"((ac)[3])          \
        : "r"(A0), "r"(A1), "r"(A2), "r"(A3), "r"(B0), "r"(B1))

__device__ __forceinline__ void cp_async16(uint32_t saddr, const void* gptr) {
    asm volatile("cp.async.ca.shared.global [%0], [%1], 16;"
                 :: "r"(saddr), "l"(gptr) : "memory");
}

extern __shared__ __align__(128) char sm[];

__global__ __launch_bounds__(256, 3)
void kan_fp16_kernel(const float* __restrict__ x, const float* __restrict__ bias,
                     float* __restrict__ y, int batch) {
    const int tid  = threadIdx.x;
    const int lane = tid & 31;
    const int wid  = tid >> 5;
    const int wm   = wid & 3;          // m32 group (rows wm*32..+31)
    const int wn   = wid >> 2;         // n32 group (cols wn*32..+31)
    const int rowBase = blockIdx.x * M_TILE;
    const uint32_t sbase = (uint32_t)__cvta_generic_to_shared(sm);

    // ---- gen mapping: adjacent lanes = two halves of the SAME row, so the
    // per-warp x LDG touches 16 lines (2 lanes / 128B line), not 32 ----
    const int grow = tid >> 1;                   // row 0..127
    const int half = tid & 1;                    // feats half*4 .. half*4+3
    const int mt_g = grow >> 4;
    const int rh_g = (grow >> 3) & 1;
    const int fr_g = grow & 7;
    int rg = rowBase + grow; if (rg > batch - 1) rg = batch - 1;
    const float* xrow = x + (size_t)rg * N_IN + half * 4;

    // ---- consumer fragment indices ----
    const int c  = lane & 3;
    const int fr = lane >> 2;

    float acc[2][4][4] = {};

    // ---- prolog: cp.async stage B(0), prefetch x(0) ----
    {
        const char* src = (const char*)g_Bpack;
        cp_async16(sbase + SMB(0) + tid * 16,         src + tid * 16);
        cp_async16(sbase + SMB(0) + (tid + 256) * 16, src + (tid + 256) * 16);
        asm volatile("cp.async.commit_group;" ::: "memory");
    }
    float4 xv = *(const float4*)xrow;

    for (int ch = 0; ch < N_CHUNKS; ch++) {
        const int p = ch & 1;

        // ---- generate A(ch): tanh + Legendre, swizzled fragment layout ----
        {
            char* Ab = sm + SMA(p);
            float xf[4] = {xv.x, xv.y, xv.z, xv.w};
            if (ch + 1 < N_CHUNKS) xv = *(const float4*)(xrow + (ch + 1) * 8);

            uint32_t hp[4][4];                         // [feat][c-pair] half2 bits
            #pragma unroll
            for (int f = 0; f < 4; f++) {
                float e2 = __expf(2.0f * xf[f]);
                float t  = 1.0f - 2.0f / (e2 + 1.0f);
                float pv[8];
                pv[0] = t;
                float pp = 1.0f, pc = t;
                #pragma unroll
                for (int d = 1; d < 8; d++) {
                    float kk = (float)(d + 1);
                    float a_ = (2.0f * kk - 1.0f) / kk;
                    float b_ = (kk - 1.0f) / kk;
                    float pn = a_ * t * pc - b_ * pp;
                    pv[d] = pn; pp = pc; pc = pn;
                }
                #pragma unroll
                for (int cc = 0; cc < 4; cc++) {
                    __half2 h2 = __floats2half2_rn(pv[2 * cc], pv[2 * cc + 1]);
                    hp[cc == 0 ? f : f][cc] = *(uint32_t*)&h2;   // hp[f][cc]
                }
            }
            // write (i0,i1) pairs: block (ks, mt)*512B, slot ASWZ3*16 + rh*8
            #pragma unroll
            for (int p2 = 0; p2 < 2; p2++) {
                int ks = half * 2 + p2;
                char* blk = Ab + (ks * 8 + mt_g) * 512 + rh_g * 8;
                #pragma unroll
                for (int cc = 0; cc < 4; cc++) {
                    uint2 v = make_uint2(hp[p2 * 2][cc], hp[p2 * 2 + 1][cc]);
                    *(uint2*)(blk + ASWZ3(fr_g, cc, ks) * 16) = v;
                }
            }
        }

        // ---- B(ch) arrived + A(ch) visible ----
        asm volatile("cp.async.wait_group 0;" ::: "memory");
        __syncthreads();

        // ---- prefetch B(ch+1) (safe: all warps finished MMA(ch-1)) ----
        if (ch + 1 < N_CHUNKS) {
            const char* src = (const char*)g_Bpack + (size_t)(ch + 1) * 8192;
            cp_async16(sbase + SMB(p ^ 1) + tid * 16,         src + tid * 16);
            cp_async16(sbase + SMB(p ^ 1) + (tid + 256) * 16, src + (tid + 256) * 16);
            asm volatile("cp.async.commit_group;" ::: "memory");
        }

        // ---- MMA: 4 k-steps x (2 m-tiles x 4 n-tiles) m16n8k16 ----
        {
            const char* Ar = sm + SMA(p);
            const char* Br = sm + SMB(p);
            #pragma unroll
            for (int ks = 0; ks < 4; ks++) {
                uint4 a0 = *(const uint4*)(Ar + (ks * 8 + wm * 2 + 0) * 512 + ASWZ3(fr, c, ks) * 16);
                uint4 a1 = *(const uint4*)(Ar + (ks * 8 + wm * 2 + 1) * 512 + ASWZ3(fr, c, ks) * 16);
                uint4 b0 = *(const uint4*)(Br + ((ks * 4 + wn * 2 + 0) * 32 + lane) * 16);
                uint4 b1 = *(const uint4*)(Br + ((ks * 4 + wn * 2 + 1) * 32 + lane) * 16);
                // A operand order: (rl-klo, rh-klo, rl-khi, rh-khi) = (x, z, y, w)
                MMA16816(acc[0][0], a0.x, a0.z, a0.y, a0.w, b0.x, b0.y);
                MMA16816(acc[0][1], a0.x, a0.z, a0.y, a0.w, b0.z, b0.w);
                MMA16816(acc[0][2], a0.x, a0.z, a0.y, a0.w, b1.x, b1.y);
                MMA16816(acc[0][3], a0.x, a0.z, a0.y, a0.w, b1.z, b1.w);
                MMA16816(acc[1][0], a1.x, a1.z, a1.y, a1.w, b0.x, b0.y);
                MMA16816(acc[1][1], a1.x, a1.z, a1.y, a1.w, b0.z, b0.w);
                MMA16816(acc[1][2], a1.x, a1.z, a1.y, a1.w, b1.x, b1.y);
                MMA16816(acc[1][3], a1.x, a1.z, a1.y, a1.w, b1.z, b1.w);
            }
        }
    }

    // ---- epilogue: bias + store ----
    #pragma unroll
    for (int t = 0; t < 2; t++) {
        int r0 = rowBase + wm * 32 + t * 16 + fr;
        #pragma unroll
        for (int nt = 0; nt < 4; nt++) {
            int col = wn * 32 + nt * 8 + c * 2;
            float2 bb = *(const float2*)(bias + col);
            if (r0 < batch)
                *(float2*)(y + (size_t)r0 * N_OUT + col) =
                    make_float2(acc[t][nt][0] + bb.x, acc[t][nt][1] + bb.y);
            if (r0 + 8 < batch)
                *(float2*)(y + (size_t)(r0 + 8) * N_OUT + col) =
                    make_float2(acc[t][nt][2] + bb.x, acc[t][nt][3] + bb.y);
        }
    }
}

extern "C" void kernel_launch(void* const* d_in, const int* in_sizes, int n_in,
                              void* d_out, int out_size) {
    const float* x       = (const float*)d_in[0];
    const float* c_basis = (const float*)d_in[1];
    const float* bias    = (const float*)d_in[2];
    float* y = (float*)d_out;
    int batch = in_sizes[0] / N_IN;

    cudaFuncSetAttribute(kan_fp16_kernel,
                         cudaFuncAttributeMaxDynamicSharedMemorySize, SM_TOTAL);

    repack_kernel<<<(N_CHUNKS * 4096) / 256, 256>>>(c_basis);
    int grid = (batch + M_TILE - 1) / M_TILE;
    kan_fp16_kernel<<<grid, 256, SM_TOTAL>>>(x, bias, y, batch);
}

// round 8
// speedup vs baseline: 1.1879x; 1.0412x over previous
#include <cuda_runtime.h>
#include <cuda_fp16.h>
#include <cstdint>

#define N_IN     256
#define DDEG     8
#define N_OUT    64
#define M_TILE   128
#define N_CHUNKS 32

// smem byte offsets: A double-buffered 16KB each, B 8KB each
#define SMA(p)   ((p) * 16384)
#define SMB(p)   (32768 + (p) * 8192)
#define SM_TOTAL 49152

// A-tile in-block swizzle: slot for (fr, c) within a (ks, mtile) 512B block.
#define ASWZ3(fr, c, ks) ((((fr) + 2 * (c) + 4 * (((ks) >> 1) & 1)) & 7) + 8 * (c))

// B prepacked as exact per-chunk smem fragment images: 32 chunks x 4096 halves
__device__ __half g_Bpack[N_CHUNKS * 4096];

// Layout: [ch][ks(4)][ng(4)][lane(32)][e(8 halves)]; uint4 slot = frags of
// n-tiles {2ng, 2ng+1}: {nt0.b01, nt0.b23, nt1.b01, nt1.b23}
__global__ void repack_kernel(const float* __restrict__ c_basis) {
    int idx = blockIdx.x * 256 + threadIdx.x;          // 131072 total
    int e    = idx & 7;
    int lane = (idx >> 3) & 31;
    int ng   = (idx >> 8) & 3;
    int ks   = (idx >> 10) & 3;
    int ch   = idx >> 12;
    int nt = ng * 2 + (e >> 2);
    int bp = (e >> 1) & 1;                             // b01 vs b23 (k +8)
    int h  = e & 1;
    int k  = ks * 16 + bp * 8 + (lane & 3) * 2 + h;    // k within chunk
    int n  = nt * 8 + (lane >> 2);
    int kg = ch * 64 + k;
    int i = kg >> 3, d = kg & 7;
    g_Bpack[idx] = __float2half_rn(c_basis[(n * N_IN + i) * DDEG + d]);
}

#define MMA16816(ac, A0, A1, A2, A3, B0, B1)                                  \
    asm volatile(                                                             \
        "mma.sync.aligned.m16n8k16.row.col.f32.f16.f16.f32 "                  \
        "{%0,%1,%2,%3}, {%4,%5,%6,%7}, {%8,%9}, {%0,%1,%2,%3};"               \
        : "+f"((ac)[0]), "+f"((ac)[1]), "+f"((ac)[2]), "+f"((ac)[3])          \
        : "r"(A0), "r"(A1), "r"(A2), "r"(A3), "r"(B0), "r"(B1))

__device__ __forceinline__ void cp_async16(uint32_t saddr, const void* gptr) {
    asm volatile("cp.async.ca.shared.global [%0], [%1], 16;"
                 :: "r"(saddr), "l"(gptr) : "memory");
}

extern __shared__ __align__(128) char sm[];

__global__ __launch_bounds__(256, 3)
void kan_fp16_kernel(const float* __restrict__ x, const float* __restrict__ bias,
                     float* __restrict__ y, int batch) {
    const int tid  = threadIdx.x;
    const int lane = tid & 31;
    const int wid  = tid >> 5;
    const int wm   = wid & 3;          // m32 group (rows wm*32..+31)
    const int wn   = wid >> 2;         // n32 group (cols wn*32..+31)
    const int rowBase = blockIdx.x * M_TILE;
    const uint32_t sbase = (uint32_t)__cvta_generic_to_shared(sm);

    // ---- gen mapping: adjacent lanes = two halves of the SAME row, so the
    // per-warp x LDG touches 16 lines (2 lanes / 128B line), not 32 ----
    const int grow = tid >> 1;                   // row 0..127
    const int half = tid & 1;                    // feats half*4 .. half*4+3
    const int mt_g = grow >> 4;
    const int rh_g = (grow >> 3) & 1;
    const int fr_g = grow & 7;
    int rg = rowBase + grow; if (rg > batch - 1) rg = batch - 1;
    const float* xrow = x + (size_t)rg * N_IN + half * 4;
    // STS byte-half: rh ^ half (= rh ^ (ks>>1)) -> even lanes fill low 8B,
    // odd lanes high 8B of every quad -> 32 banks, conflict-free.
    const int sh_g = (rh_g ^ half) * 8;

    // ---- consumer fragment indices ----
    const int c  = lane & 3;
    const int fr = lane >> 2;

    float acc[2][4][4] = {};

    // ---- prolog: cp.async stage B(0), prefetch x(0) ----
    {
        const char* src = (const char*)g_Bpack;
        cp_async16(sbase + SMB(0) + tid * 16,         src + tid * 16);
        cp_async16(sbase + SMB(0) + (tid + 256) * 16, src + (tid + 256) * 16);
        asm volatile("cp.async.commit_group;" ::: "memory");
    }
    float4 xv = *(const float4*)xrow;

    for (int ch = 0; ch < N_CHUNKS; ch++) {
        const int p = ch & 1;

        // ---- generate A(ch): tanh + Legendre, swizzled fragment layout ----
        {
            char* Ab = sm + SMA(p);
            float xf[4] = {xv.x, xv.y, xv.z, xv.w};
            if (ch + 1 < N_CHUNKS) xv = *(const float4*)(xrow + (ch + 1) * 8);

            uint32_t hp[4][4];                         // [feat][c-pair] half2 bits
            #pragma unroll
            for (int f = 0; f < 4; f++) {
                float e2 = __expf(2.0f * xf[f]);
                float t  = 1.0f - 2.0f / (e2 + 1.0f);
                float pv[8];
                pv[0] = t;
                float pp = 1.0f, pc = t;
                #pragma unroll
                for (int d = 1; d < 8; d++) {
                    float kk = (float)(d + 1);
                    float a_ = (2.0f * kk - 1.0f) / kk;
                    float b_ = (kk - 1.0f) / kk;
                    float pn = a_ * t * pc - b_ * pp;
                    pv[d] = pn; pp = pc; pc = pn;
                }
                #pragma unroll
                for (int cc = 0; cc < 4; cc++) {
                    __half2 h2 = __floats2half2_rn(pv[2 * cc], pv[2 * cc + 1]);
                    hp[f][cc] = *(uint32_t*)&h2;
                }
            }
            // write (i0,i1) pairs: block (ks, mt)*512B, slot ASWZ3*16 + sh_g
            #pragma unroll
            for (int p2 = 0; p2 < 2; p2++) {
                int ks = half * 2 + p2;
                char* blk = Ab + (ks * 8 + mt_g) * 512 + sh_g;
                #pragma unroll
                for (int cc = 0; cc < 4; cc++) {
                    uint2 v = make_uint2(hp[p2 * 2][cc], hp[p2 * 2 + 1][cc]);
                    *(uint2*)(blk + ASWZ3(fr_g, cc, ks) * 16) = v;
                }
            }
        }

        // ---- B(ch) arrived + A(ch) visible ----
        asm volatile("cp.async.wait_group 0;" ::: "memory");
        __syncthreads();

        // ---- prefetch B(ch+1) (safe: all warps finished MMA(ch-1)) ----
        if (ch + 1 < N_CHUNKS) {
            const char* src = (const char*)g_Bpack + (size_t)(ch + 1) * 8192;
            cp_async16(sbase + SMB(p ^ 1) + tid * 16,         src + tid * 16);
            cp_async16(sbase + SMB(p ^ 1) + (tid + 256) * 16, src + (tid + 256) * 16);
            asm volatile("cp.async.commit_group;" ::: "memory");
        }

        // ---- MMA: 4 k-steps x (2 m-tiles x 4 n-tiles) m16n8k16 ----
        // ks<2: slot = (rl.i0, rl.i1, rh.i0, rh.i1) -> A order (x,z,y,w)
        // ks>=2: halves swapped by sh_g -> slot = (rh.i0, rh.i1, rl.i0, rl.i1)
        //        -> A order (z,x,w,y)
        {
            const char* Ar = sm + SMA(p);
            const char* Br = sm + SMB(p);
            #pragma unroll
            for (int ks = 0; ks < 4; ks++) {
                uint4 a0 = *(const uint4*)(Ar + (ks * 8 + wm * 2 + 0) * 512 + ASWZ3(fr, c, ks) * 16);
                uint4 a1 = *(const uint4*)(Ar + (ks * 8 + wm * 2 + 1) * 512 + ASWZ3(fr, c, ks) * 16);
                uint4 b0 = *(const uint4*)(Br + ((ks * 4 + wn * 2 + 0) * 32 + lane) * 16);
                uint4 b1 = *(const uint4*)(Br + ((ks * 4 + wn * 2 + 1) * 32 + lane) * 16);
                if (ks < 2) {
                    MMA16816(acc[0][0], a0.x, a0.z, a0.y, a0.w, b0.x, b0.y);
                    MMA16816(acc[0][1], a0.x, a0.z, a0.y, a0.w, b0.z, b0.w);
                    MMA16816(acc[0][2], a0.x, a0.z, a0.y, a0.w, b1.x, b1.y);
                    MMA16816(acc[0][3], a0.x, a0.z, a0.y, a0.w, b1.z, b1.w);
                    MMA16816(acc[1][0], a1.x, a1.z, a1.y, a1.w, b0.x, b0.y);
                    MMA16816(acc[1][1], a1.x, a1.z, a1.y, a1.w, b0.z, b0.w);
                    MMA16816(acc[1][2], a1.x, a1.z, a1.y, a1.w, b1.x, b1.y);
                    MMA16816(acc[1][3], a1.x, a1.z, a1.y, a1.w, b1.z, b1.w);
                } else {
                    MMA16816(acc[0][0], a0.z, a0.x, a0.w, a0.y, b0.x, b0.y);
                    MMA16816(acc[0][1], a0.z, a0.x, a0.w, a0.y, b0.z, b0.w);
                    MMA16816(acc[0][2], a0.z, a0.x, a0.w, a0.y, b1.x, b1.y);
                    MMA16816(acc[0][3], a0.z, a0.x, a0.w, a0.y, b1.z, b1.w);
                    MMA16816(acc[1][0], a1.z, a1.x, a1.w, a1.y, b0.x, b0.y);
                    MMA16816(acc[1][1], a1.z, a1.x, a1.w, a1.y, b0.z, b0.w);
                    MMA16816(acc[1][2], a1.z, a1.x, a1.w, a1.y, b1.x, b1.y);
                    MMA16816(acc[1][3], a1.z, a1.x, a1.w, a1.y, b1.z, b1.w);
                }
            }
        }
    }

    // ---- epilogue: bias + store ----
    #pragma unroll
    for (int t = 0; t < 2; t++) {
        int r0 = rowBase + wm * 32 + t * 16 + fr;
        #pragma unroll
        for (int nt = 0; nt < 4; nt++) {
            int col = wn * 32 + nt * 8 + c * 2;
            float2 bb = *(const float2*)(bias + col);
            if (r0 < batch)
                *(float2*)(y + (size_t)r0 * N_OUT + col) =
                    make_float2(acc[t][nt][0] + bb.x, acc[t][nt][1] + bb.y);
            if (r0 + 8 < batch)
                *(float2*)(y + (size_t)(r0 + 8) * N_OUT + col) =
                    make_float2(acc[t][nt][2] + bb.x, acc[t][nt][3] + bb.y);
        }
    }
}

extern "C" void kernel_launch(void* const* d_in, const int* in_sizes, int n_in,
                              void* d_out, int out_size) {
    const float* x       = (const float*)d_in[0];
    const float* c_basis = (const float*)d_in[1];
    const float* bias    = (const float*)d_in[2];
    float* y = (float*)d_out;
    int batch = in_sizes[0] / N_IN;

    cudaFuncSetAttribute(kan_fp16_kernel,
                         cudaFuncAttributeMaxDynamicSharedMemorySize, SM_TOTAL);

    repack_kernel<<<(N_CHUNKS * 4096) / 256, 256>>>(c_basis);
    int grid = (batch + M_TILE - 1) / M_TILE;
    kan_fp16_kernel<<<grid, 256, SM_TOTAL>>>(x, bias, y, batch);
}

// round 9
// speedup vs baseline: 1.2160x; 1.0237x over previous
#include <cuda_runtime.h>
#include <cuda_fp16.h>
#include <cstdint>

#define N_IN     256
#define DDEG     8
#define N_OUT    64
#define M_TILE   128
#define N_CHUNKS 32

// smem byte offsets: A double-buffered 16KB each, B 8KB each
#define SMA(p)   ((p) * 16384)
#define SMB(p)   (32768 + (p) * 8192)
#define SM_TOTAL 49152

// A-tile in-block swizzle: slot for (fr, c) within a (ks, mtile) 512B block.
#define ASWZ3(fr, c, ks) ((((fr) + 2 * (c) + 4 * (((ks) >> 1) & 1)) & 7) + 8 * (c))

// B prepacked as exact per-chunk smem fragment images: 32 chunks x 4096 halves
__device__ __half g_Bpack[N_CHUNKS * 4096];

// Layout: [ch][ks(4)][ng(4)][lane(32)][e(8 halves)]; uint4 slot = frags of
// n-tiles {2ng, 2ng+1}: {nt0.b01, nt0.b23, nt1.b01, nt1.b23}
__global__ void repack_kernel(const float* __restrict__ c_basis) {
    int idx = blockIdx.x * 256 + threadIdx.x;          // 131072 total
    int e    = idx & 7;
    int lane = (idx >> 3) & 31;
    int ng   = (idx >> 8) & 3;
    int ks   = (idx >> 10) & 3;
    int ch   = idx >> 12;
    int nt = ng * 2 + (e >> 2);
    int bp = (e >> 1) & 1;                             // b01 vs b23 (k +8)
    int h  = e & 1;
    int k  = ks * 16 + bp * 8 + (lane & 3) * 2 + h;    // k within chunk
    int n  = nt * 8 + (lane >> 2);
    int kg = ch * 64 + k;
    int i = kg >> 3, d = kg & 7;
    g_Bpack[idx] = __float2half_rn(c_basis[(n * N_IN + i) * DDEG + d]);
}

#define MMA16816(ac, A0, A1, A2, A3, B0, B1)                                  \
    asm volatile(                                                             \
        "mma.sync.aligned.m16n8k16.row.col.f32.f16.f16.f32 "                  \
        "{%0,%1,%2,%3}, {%4,%5,%6,%7}, {%8,%9}, {%0,%1,%2,%3};"               \
        : "+f"((ac)[0]), "+f"((ac)[1]), "+f"((ac)[2]), "+f"((ac)[3])          \
        : "r"(A0), "r"(A1), "r"(A2), "r"(A3), "r"(B0), "r"(B1))

__device__ __forceinline__ void cp_async16(uint32_t saddr, const void* gptr) {
    asm volatile("cp.async.ca.shared.global [%0], [%1], 16;"
                 :: "r"(saddr), "l"(gptr) : "memory");
}

// Generate this thread's A-slots for one chunk: 1 row x 4 feats -> 8 STS.64.
// Conflict-free per round-8 layout (sh_g = (rh ^ half)*8 byte-half).
__device__ __forceinline__ void gen_tile(char* Ab, float4 xv,
                                         int mt_g, int fr_g, int half, int sh_g) {
    float xf[4] = {xv.x, xv.y, xv.z, xv.w};
    uint32_t hp[4][4];                         // [feat][c-pair] half2 bits
    #pragma unroll
    for (int f = 0; f < 4; f++) {
        float e2 = __expf(2.0f * xf[f]);
        float t  = 1.0f - __fdividef(2.0f, e2 + 1.0f);
        float pv[8];
        pv[0] = t;
        float pp = 1.0f, pc = t;
        #pragma unroll
        for (int d = 1; d < 8; d++) {
            float kk = (float)(d + 1);
            float a_ = (2.0f * kk - 1.0f) / kk;
            float b_ = (kk - 1.0f) / kk;
            float pn = a_ * t * pc - b_ * pp;
            pv[d] = pn; pp = pc; pc = pn;
        }
        #pragma unroll
        for (int cc = 0; cc < 4; cc++) {
            __half2 h2 = __floats2half2_rn(pv[2 * cc], pv[2 * cc + 1]);
            hp[f][cc] = *(uint32_t*)&h2;
        }
    }
    #pragma unroll
    for (int p2 = 0; p2 < 2; p2++) {
        int ks = half * 2 + p2;
        char* blk = Ab + (ks * 8 + mt_g) * 512 + sh_g;
        #pragma unroll
        for (int cc = 0; cc < 4; cc++) {
            uint2 v = make_uint2(hp[p2 * 2][cc], hp[p2 * 2 + 1][cc]);
            *(uint2*)(blk + ASWZ3(fr_g, cc, ks) * 16) = v;
        }
    }
}

extern __shared__ __align__(128) char sm[];

__global__ __launch_bounds__(256, 2)
void kan_fp16_kernel(const float* __restrict__ x, const float* __restrict__ bias,
                     float* __restrict__ y, int batch) {
    const int tid  = threadIdx.x;
    const int lane = tid & 31;
    const int wid  = tid >> 5;
    const int wm   = wid & 3;          // m32 group (rows wm*32..+31)
    const int wn   = wid >> 2;         // n32 group (cols wn*32..+31)
    const int rowBase = blockIdx.x * M_TILE;
    const uint32_t sbase = (uint32_t)__cvta_generic_to_shared(sm);

    // ---- gen mapping: adjacent lanes = two halves of the SAME row ----
    const int grow = tid >> 1;                   // row 0..127
    const int half = tid & 1;                    // feats half*4 .. half*4+3
    const int mt_g = grow >> 4;
    const int rh_g = (grow >> 3) & 1;
    const int fr_g = grow & 7;
    int rg = rowBase + grow; if (rg > batch - 1) rg = batch - 1;
    const float* xrow = x + (size_t)rg * N_IN + half * 4;
    const int sh_g = (rh_g ^ half) * 8;

    // ---- consumer fragment indices ----
    const int c  = lane & 3;
    const int fr = lane >> 2;

    float acc[2][4][4] = {};

    // ---- prolog: stage B(0), gen A(0) ----
    {
        const char* src = (const char*)g_Bpack;
        cp_async16(sbase + SMB(0) + tid * 16,         src + tid * 16);
        cp_async16(sbase + SMB(0) + (tid + 256) * 16, src + (tid + 256) * 16);
        asm volatile("cp.async.commit_group;" ::: "memory");
    }
    float4 xv = *(const float4*)xrow;
    {
        float4 x0 = xv;
        xv = *(const float4*)(xrow + 8);               // prefetch ch=1
        gen_tile(sm + SMA(0), x0, mt_g, fr_g, half, sh_g);
    }
    asm volatile("cp.async.wait_group 0;" ::: "memory");
    __syncthreads();

    for (int ch = 0; ch < N_CHUNKS; ch++) {
        const int p = ch & 1;

        // ---- same barrier window: gen(ch+1) -> p^1 interleaves with MMA(ch) ----
        if (ch + 1 < N_CHUNKS) {
            const char* src = (const char*)g_Bpack + (size_t)(ch + 1) * 8192;
            cp_async16(sbase + SMB(p ^ 1) + tid * 16,         src + tid * 16);
            cp_async16(sbase + SMB(p ^ 1) + (tid + 256) * 16, src + (tid + 256) * 16);
            asm volatile("cp.async.commit_group;" ::: "memory");

            float4 xc = xv;
            if (ch + 2 < N_CHUNKS) xv = *(const float4*)(xrow + (ch + 2) * 8);
            gen_tile(sm + SMA(p ^ 1), xc, mt_g, fr_g, half, sh_g);
        }

        // ---- MMA(ch): 4 k-steps x (2 m-tiles x 4 n-tiles) m16n8k16 ----
        // ks<2: slot = (rl.i0, rl.i1, rh.i0, rh.i1) -> A order (x,z,y,w)
        // ks>=2: byte-halves swapped -> A order (z,x,w,y)
        {
            const char* Ar = sm + SMA(p);
            const char* Br = sm + SMB(p);
            #pragma unroll
            for (int ks = 0; ks < 4; ks++) {
                uint4 a0 = *(const uint4*)(Ar + (ks * 8 + wm * 2 + 0) * 512 + ASWZ3(fr, c, ks) * 16);
                uint4 a1 = *(const uint4*)(Ar + (ks * 8 + wm * 2 + 1) * 512 + ASWZ3(fr, c, ks) * 16);
                uint4 b0 = *(const uint4*)(Br + ((ks * 4 + wn * 2 + 0) * 32 + lane) * 16);
                uint4 b1 = *(const uint4*)(Br + ((ks * 4 + wn * 2 + 1) * 32 + lane) * 16);
                if (ks < 2) {
                    MMA16816(acc[0][0], a0.x, a0.z, a0.y, a0.w, b0.x, b0.y);
                    MMA16816(acc[0][1], a0.x, a0.z, a0.y, a0.w, b0.z, b0.w);
                    MMA16816(acc[0][2], a0.x, a0.z, a0.y, a0.w, b1.x, b1.y);
                    MMA16816(acc[0][3], a0.x, a0.z, a0.y, a0.w, b1.z, b1.w);
                    MMA16816(acc[1][0], a1.x, a1.z, a1.y, a1.w, b0.x, b0.y);
                    MMA16816(acc[1][1], a1.x, a1.z, a1.y, a1.w, b0.z, b0.w);
                    MMA16816(acc[1][2], a1.x, a1.z, a1.y, a1.w, b1.x, b1.y);
                    MMA16816(acc[1][3], a1.x, a1.z, a1.y, a1.w, b1.z, b1.w);
                } else {
                    MMA16816(acc[0][0], a0.z, a0.x, a0.w, a0.y, b0.x, b0.y);
                    MMA16816(acc[0][1], a0.z, a0.x, a0.w, a0.y, b0.z, b0.w);
                    MMA16816(acc[0][2], a0.z, a0.x, a0.w, a0.y, b1.x, b1.y);
                    MMA16816(acc[0][3], a0.z, a0.x, a0.w, a0.y, b1.z, b1.w);
                    MMA16816(acc[1][0], a1.z, a1.x, a1.w, a1.y, b0.x, b0.y);
                    MMA16816(acc[1][1], a1.z, a1.x, a1.w, a1.y, b0.z, b0.w);
                    MMA16816(acc[1][2], a1.z, a1.x, a1.w, a1.y, b1.x, b1.y);
                    MMA16816(acc[1][3], a1.z, a1.x, a1.w, a1.y, b1.z, b1.w);
                }
            }
        }

        if (ch + 1 < N_CHUNKS)
            asm volatile("cp.async.wait_group 0;" ::: "memory");
        __syncthreads();
    }

    // ---- epilogue: bias + store ----
    #pragma unroll
    for (int t = 0; t < 2; t++) {
        int r0 = rowBase + wm * 32 + t * 16 + fr;
        #pragma unroll
        for (int nt = 0; nt < 4; nt++) {
            int col = wn * 32 + nt * 8 + c * 2;
            float2 bb = *(const float2*)(bias + col);
            if (r0 < batch)
                *(float2*)(y + (size_t)r0 * N_OUT + col) =
                    make_float2(acc[t][nt][0] + bb.x, acc[t][nt][1] + bb.y);
            if (r0 + 8 < batch)
                *(float2*)(y + (size_t)(r0 + 8) * N_OUT + col) =
                    make_float2(acc[t][nt][2] + bb.x, acc[t][nt][3] + bb.y);
        }
    }
}

extern "C" void kernel_launch(void* const* d_in, const int* in_sizes, int n_in,
                              void* d_out, int out_size) {
    const float* x       = (const float*)d_in[0];
    const float* c_basis = (const float*)d_in[1];
    const float* bias    = (const float*)d_in[2];
    float* y = (float*)d_out;
    int batch = in_sizes[0] / N_IN;

    cudaFuncSetAttribute(kan_fp16_kernel,
                         cudaFuncAttributeMaxDynamicSharedMemorySize, SM_TOTAL);

    repack_kernel<<<(N_CHUNKS * 4096) / 256, 256>>>(c_basis);
    int grid = (batch + M_TILE - 1) / M_TILE;
    kan_fp16_kernel<<<grid, 256, SM_TOTAL>>>(x, bias, y, batch);
}